// round 9
// baseline (speedup 1.0000x reference)
#include <cuda_runtime.h>
#include <math.h>
#include <stdint.h>

#define D_DIM 1024
#define H_DIM 1024
#define E_DIM 64
#define M_TOTAL 65536
#define G1_TILES ((M_TOTAL / 128) * (H_DIM / 256))     // 2048 (fallback)
#define PAIR_TILES ((M_TOTAL / 256) * (H_DIM / 256))   // 1024 (cg2)

#if defined(__CUDA_ARCH__) && (__CUDA_ARCH__ >= 1000) && \
    (defined(__CUDA_ARCH_FEAT_SM103_ALL) || defined(__CUDA_ARCH_FEAT_SM100_ALL) || \
     defined(__CUDA_ARCH_SPECIFIC__) || defined(__CUDA_ARCH_FAMILY_SPECIFIC__))
#define HAS_TCGEN05 1
#else
#define HAS_TCGEN05 0
#endif

__device__ float g_H[(size_t)M_TOTAL * H_DIM];   // 256 MB hidden activations

// ---------------- PTX helpers ------------------------------------------------
__device__ __forceinline__ uint32_t smem_u32(const void* p) {
    uint32_t a;
    asm("{ .reg .u64 t; cvta.to.shared.u64 t, %1; cvt.u32.u64 %0, t; }"
        : "=r"(a) : "l"(p));
    return a;
}
__device__ __forceinline__ uint32_t cluster_rank() {
    uint32_t r;
    asm("mov.u32 %0, %%cluster_ctarank;" : "=r"(r));
    return r;
}

#define SWZ128(o) ((o) ^ (((o) >> 3) & 0x70))

__device__ __forceinline__ void mbar_init(uint32_t mbar, uint32_t cnt) {
    asm volatile("mbarrier.init.shared.b64 [%0], %1;" :: "r"(mbar), "r"(cnt) : "memory");
}
__device__ __forceinline__ void mbar_wait(uint32_t mbar, uint32_t parity) {
    asm volatile(
        "{\n\t"
        ".reg .pred P;\n\t"
        "WL%=:\n\t"
        "mbarrier.try_wait.parity.shared::cta.b64 P, [%0], %1, 0x989680;\n\t"
        "@P bra WD%=;\n\t"
        "bra WL%=;\n\t"
        "WD%=:\n\t"
        "}"
        :: "r"(mbar), "r"(parity) : "memory");
}
__device__ __forceinline__ void mbar_arrive(uint32_t mbar) {
    asm volatile("mbarrier.arrive.shared.b64 _, [%0];" :: "r"(mbar) : "memory");
}
// Arrive on the leader (rank 0) CTA's mbarrier at the same smem offset.
__device__ __forceinline__ void mbar_arrive_leader(uint32_t local_mbar) {
    asm volatile(
        "{\n\t"
        ".reg .b32 ra;\n\t"
        "mapa.shared::cluster.u32 ra, %0, 0;\n\t"
        "mbarrier.arrive.shared::cluster.b64 _, [ra];\n\t"
        "}"
        :: "r"(local_mbar) : "memory");
}
__device__ __forceinline__ void fence_proxy_async_gen() {
    asm volatile("fence.proxy.async;" ::: "memory");
}
__device__ __forceinline__ void fence_proxy_async_cta() {
    asm volatile("fence.proxy.async.shared::cta;" ::: "memory");
}
__device__ __forceinline__ void cluster_sync() {
    asm volatile("barrier.cluster.arrive.aligned;" ::: "memory");
    asm volatile("barrier.cluster.wait.aligned;" ::: "memory");
}

__device__ __forceinline__ float tf32_rnd(float a) {
    uint32_t r;
    asm("cvt.rna.tf32.f32 %0, %1;" : "=r"(r) : "f"(a));
    return __uint_as_float(r);
}
__device__ __forceinline__ void split4(float4 v, float4& h, float4& l) {
    h.x = tf32_rnd(v.x); l.x = tf32_rnd(v.x - h.x);
    h.y = tf32_rnd(v.y); l.y = tf32_rnd(v.y - h.y);
    h.z = tf32_rnd(v.z); l.z = tf32_rnd(v.z - h.z);
    h.w = tf32_rnd(v.w); l.w = tf32_rnd(v.w - h.w);
}

#if HAS_TCGEN05
__device__ __forceinline__ uint64_t make_desc_sw128(uint32_t addr) {
    const uint64_t base = (2ull << 61) | (1ull << 46) | (64ull << 32) | (1ull << 16);
    return base | ((uint64_t)(addr >> 4) & 0x3FFF);
}
__device__ __forceinline__ void mma_tf32_ss(uint32_t d_tmem, uint64_t a_desc,
                                            uint64_t b_desc, uint32_t idesc,
                                            uint32_t enable_d) {
    asm volatile(
        "{\n\t"
        ".reg .pred p;\n\t"
        "setp.ne.u32 p, %5, 0;\n\t"
        "tcgen05.mma.cta_group::1.kind::tf32 [%0], %1, %2, %3, {%4, %4, %4, %4}, p;\n\t"
        "}"
        :: "r"(d_tmem), "l"(a_desc), "l"(b_desc), "r"(idesc), "r"(0u), "r"(enable_d)
        : "memory");
}
__device__ __forceinline__ void mma_tf32_ss_cg2(uint32_t d_tmem, uint64_t a_desc,
                                                uint64_t b_desc, uint32_t idesc,
                                                uint32_t enable_d) {
    asm volatile(
        "{\n\t"
        ".reg .pred p;\n\t"
        "setp.ne.u32 p, %5, 0;\n\t"
        "tcgen05.mma.cta_group::2.kind::tf32 [%0], %1, %2, %3, "
        "{%4, %4, %4, %4, %4, %4, %4, %4}, p;\n\t"
        "}"
        :: "r"(d_tmem), "l"(a_desc), "l"(b_desc), "r"(idesc), "r"(0u), "r"(enable_d)
        : "memory");
}
__device__ __forceinline__ void tc_commit(uint32_t mbar) {
    asm volatile(
        "tcgen05.commit.cta_group::1.mbarrier::arrive::one.shared::cluster.b64 [%0];"
        :: "r"(mbar) : "memory");
}
__device__ __forceinline__ void tc_commit_mc_cg2(uint32_t mbar, uint16_t mask) {
    asm volatile(
        "tcgen05.commit.cta_group::2.mbarrier::arrive::one.shared::cluster.multicast::cluster.b64 [%0], %1;"
        :: "r"(mbar), "h"(mask) : "memory");
}
__device__ __forceinline__ void tc_alloc(uint32_t slot, uint32_t ncols) {
    asm volatile("tcgen05.alloc.cta_group::1.sync.aligned.shared::cta.b32 [%0], %1;"
                 :: "r"(slot), "r"(ncols) : "memory");
}
__device__ __forceinline__ void tc_alloc_cg2(uint32_t slot, uint32_t ncols) {
    asm volatile("tcgen05.alloc.cta_group::2.sync.aligned.shared::cta.b32 [%0], %1;"
                 :: "r"(slot), "r"(ncols) : "memory");
}
__device__ __forceinline__ void tc_dealloc(uint32_t tmem, uint32_t ncols) {
    asm volatile("tcgen05.relinquish_alloc_permit.cta_group::1.sync.aligned;");
    asm volatile("tcgen05.dealloc.cta_group::1.sync.aligned.b32 %0, %1;" :: "r"(tmem), "r"(ncols));
}
__device__ __forceinline__ void tc_dealloc_cg2(uint32_t tmem, uint32_t ncols) {
    asm volatile("tcgen05.relinquish_alloc_permit.cta_group::2.sync.aligned;");
    asm volatile("tcgen05.dealloc.cta_group::2.sync.aligned.b32 %0, %1;" :: "r"(tmem), "r"(ncols));
}
__device__ __forceinline__ void tc_fence_after() {
    asm volatile("tcgen05.fence::after_thread_sync;" ::: "memory");
}
__device__ __forceinline__ void tc_fence_before() {
    asm volatile("tcgen05.fence::before_thread_sync;" ::: "memory");
}
__device__ __forceinline__ void tc_wait_ld() {
    asm volatile("tcgen05.wait::ld.sync.aligned;" ::: "memory");
}

#define TC_LD_X32(r, a)                                                       \
    asm volatile(                                                             \
        "tcgen05.ld.sync.aligned.32x32b.x32.b32 "                             \
        "{%0, %1, %2, %3, %4, %5, %6, %7, "                                   \
        " %8, %9, %10, %11, %12, %13, %14, %15, "                             \
        " %16, %17, %18, %19, %20, %21, %22, %23, "                           \
        " %24, %25, %26, %27, %28, %29, %30, %31}, [%32];"                    \
        : "=r"((r)[0]),  "=r"((r)[1]),  "=r"((r)[2]),  "=r"((r)[3]),          \
          "=r"((r)[4]),  "=r"((r)[5]),  "=r"((r)[6]),  "=r"((r)[7]),          \
          "=r"((r)[8]),  "=r"((r)[9]),  "=r"((r)[10]), "=r"((r)[11]),         \
          "=r"((r)[12]), "=r"((r)[13]), "=r"((r)[14]), "=r"((r)[15]),         \
          "=r"((r)[16]), "=r"((r)[17]), "=r"((r)[18]), "=r"((r)[19]),         \
          "=r"((r)[20]), "=r"((r)[21]), "=r"((r)[22]), "=r"((r)[23]),         \
          "=r"((r)[24]), "=r"((r)[25]), "=r"((r)[26]), "=r"((r)[27]),         \
          "=r"((r)[28]), "=r"((r)[29]), "=r"((r)[30]), "=r"((r)[31])          \
        : "r"(a))
#endif  // HAS_TCGEN05

__device__ __forceinline__ float gelu_erf(float v) {
    return 0.5f * v * (1.0f + erff(v * 0.7071067811865476f));
}

// ============================================================================
// GEMM1 (persistent, cta_group::2): H = gelu(x @ W1^T + b1). 3xTF32.
// Pair-tile M=256 x N=256, BK=32, 2-stage ring. 416 thr/CTA:
// 256 producers | warp8 MMA-issue (leader only) | warps 9-12 epilogue.
// Per CTA smem stage: {Ah,Al,Bh,Bl} each 128 rows x 32 cols = 16 KB -> 64 KB.
// ============================================================================
#define BK 32
#define NIT (D_DIM / BK)
#define STG1_BYTES 65536
#define OFF_ALO 16384
#define OFF_BHI 32768
#define OFF_BLO 49152
#define GEMM1_SMEM (1024 + 2 * STG1_BYTES)

// cg2 idesc: dtype f32, a/b tf32, N=256, M=256
#define IDESC_CG2 ((1u << 4) | (2u << 7) | (2u << 10) | ((256u / 8) << 17) | ((256u / 16) << 24))

extern "C" __global__ void __launch_bounds__(416, 1) __cluster_dims__(2, 1, 1)
gemm1_kernel(
    const float* __restrict__ x, const float* __restrict__ W1,
    const float* __restrict__ b1, float* __restrict__ Hout)
{
    extern __shared__ __align__(1024) char smem[];
    const int tid = threadIdx.x;

#if HAS_TCGEN05
    const uint32_t sbase = smem_u32(smem);
    const uint32_t rank = cluster_rank();
    const int pair = blockIdx.x >> 1;
    const int npairs = gridDim.x >> 1;

    // mbars: full[s]=64+16s (cnt 512, leader-only used), empty[s]=72+16s (cnt 1),
    //        tdone[b]=96+16b (cnt 1), dfree[b]=104+16b (cnt 256, leader-only used)
    if (tid == 0) {
#pragma unroll
        for (int s = 0; s < 2; s++) {
            mbar_init(sbase + 64 + 16 * s, 512);
            mbar_init(sbase + 64 + 16 * s + 8, 1);
            mbar_init(sbase + 96 + 16 * s, 1);
            mbar_init(sbase + 96 + 16 * s + 8, 256);
        }
    }
    if (tid >= 256 && tid < 288) tc_alloc_cg2(sbase, 512);
    __syncthreads();
    cluster_sync();   // barriers + TMEM visible before any cross-CTA traffic

    uint32_t tmem_base;
    asm volatile("ld.shared.b32 %0, [%1];" : "=r"(tmem_base) : "r"(sbase));

    if (tid < 256) {
        // ---------------- producers: fill local A-half / B-half --------------
        const int r0 = tid >> 3;        // 0..31
        const int c4 = tid & 7;
        uint32_t off[4];
#pragma unroll
        for (int j = 0; j < 4; j++)
            off[j] = SWZ128((uint32_t)(r0 + 32 * j) * 128 + c4 * 16);

        uint32_t pe[2] = {1, 1};

        for (int t = pair; t < PAIR_TILES; t += npairs) {
            const int bm = (t >> 2) * 256 + rank * 128;
            const int bn = (t & 3) * 256 + rank * 128;
            const float* pA = x  + (size_t)(bm + r0) * D_DIM + c4 * 4;
            const float* pB = W1 + (size_t)(bn + r0) * D_DIM + c4 * 4;

            for (int i = 0; i < NIT; i++) {
                const int s = i & 1;
                const uint32_t mb_full  = sbase + 64 + 16 * s;
                const uint32_t mb_empty = mb_full + 8;
                mbar_wait(mb_empty, pe[s]); pe[s] ^= 1;

                const int k0 = i * BK;
                char* st = smem + 1024 + s * STG1_BYTES;
#pragma unroll
                for (int j = 0; j < 4; j++) {
                    float4 v = *(const float4*)(pA + (size_t)(32 * j) * D_DIM + k0);
                    float4 h, l; split4(v, h, l);
                    *(float4*)(st + off[j])           = h;
                    *(float4*)(st + OFF_ALO + off[j]) = l;
                }
#pragma unroll
                for (int j = 0; j < 4; j++) {
                    float4 v = *(const float4*)(pB + (size_t)(32 * j) * D_DIM + k0);
                    float4 h, l; split4(v, h, l);
                    *(float4*)(st + OFF_BHI + off[j]) = h;
                    *(float4*)(st + OFF_BLO + off[j]) = l;
                }
                fence_proxy_async_gen();      // order STS before peer MMA reads
                mbar_arrive_leader(mb_full);  // aggregate both CTAs on leader
            }
        }
    } else if (tid == 256 && rank == 0) {
        // ---------------- MMA issuer (leader only) ---------------------------
        uint32_t pf[2] = {0, 0}, pd[2] = {0, 0};
        int lt = 0;
        for (int t = pair; t < PAIR_TILES; t += npairs) {
            const int b = lt & 1;
            if (lt >= 2) { mbar_wait(sbase + 96 + 16 * b + 8, pd[b]); pd[b] ^= 1; }
            const uint32_t dD = tmem_base + b * 256;

            for (int i = 0; i < NIT; i++) {
                const int s = i & 1;
                const uint32_t mb_full  = sbase + 64 + 16 * s;
                const uint32_t mb_empty = mb_full + 8;
                mbar_wait(mb_full, pf[s]); pf[s] ^= 1;

                uint32_t sb = sbase + 1024 + s * STG1_BYTES;
                uint64_t dAh = make_desc_sw128(sb);
                uint64_t dAl = make_desc_sw128(sb + OFF_ALO);
                uint64_t dBh = make_desc_sw128(sb + OFF_BHI);
                uint64_t dBl = make_desc_sw128(sb + OFF_BLO);
#pragma unroll
                for (int ks = 0; ks < 4; ks++) {
                    mma_tf32_ss_cg2(dD, dAh + 2 * ks, dBh + 2 * ks, IDESC_CG2,
                                    (i == 0 && ks == 0) ? 0u : 1u);
                    mma_tf32_ss_cg2(dD, dAh + 2 * ks, dBl + 2 * ks, IDESC_CG2, 1u);
                    mma_tf32_ss_cg2(dD, dAl + 2 * ks, dBh + 2 * ks, IDESC_CG2, 1u);
                }
                tc_commit_mc_cg2(mb_empty, 0x3);      // -> both CTAs' empty[s]
            }
            tc_commit_mc_cg2(sbase + 96 + 16 * b, 0x3);  // -> both tdone[b]
            lt++;
        }
    } else if (tid >= 288) {
        // ---------------- epilogue: 4 warps, local 128 rows x 256 cols -------
        const int sub = (tid >> 5) & 3;
        const int lane = tid & 31;
        uint32_t pt[2] = {0, 0};
        int lt = 0;
        for (int t = pair; t < PAIR_TILES; t += npairs) {
            const int b = lt & 1;
            mbar_wait(sbase + 96 + 16 * b, pt[b]); pt[b] ^= 1;
            tc_fence_after();

            const int bm = (t >> 2) * 256 + rank * 128;
            const int bn = (t & 3) * 256;
            const int row = bm + sub * 32 + lane;
            float* hrow = Hout + (size_t)row * H_DIM + bn;
            const float* brow = b1 + bn;
            const uint32_t dD = tmem_base + b * 256;
#pragma unroll
            for (int ch = 0; ch < 8; ch++) {
                uint32_t r[32];
                TC_LD_X32(r, dD + ch * 32);
                tc_wait_ld();
#pragma unroll
                for (int q = 0; q < 8; q++) {
                    float4 bias = *(const float4*)(brow + ch * 32 + q * 4);
                    float4 o;
                    o.x = gelu_erf(__uint_as_float(r[q * 4 + 0]) + bias.x);
                    o.y = gelu_erf(__uint_as_float(r[q * 4 + 1]) + bias.y);
                    o.z = gelu_erf(__uint_as_float(r[q * 4 + 2]) + bias.z);
                    o.w = gelu_erf(__uint_as_float(r[q * 4 + 3]) + bias.w);
                    *(float4*)(hrow + ch * 32 + q * 4) = o;
                }
            }
            tc_fence_before();
            mbar_arrive_leader(sbase + 96 + 16 * b + 8);  // dfree[b] on leader
            lt++;
        }
    }

    __syncthreads();
    cluster_sync();   // all work (incl. peer smem reads) done before dealloc
    if (tid >= 256 && tid < 288) tc_dealloc_cg2(tmem_base, 512);
    cluster_sync();

#else  // ---------- FFMA fallback (generic pass; persistent) -----------------
    float* As = (float*)smem;
    float* Bs = As + 8 * 128;

    const int tx = tid & 15;
    const int ty = tid >> 4;
    const int lr = tid >> 1;
    const int lc = (tid & 1) * 4;

    for (int t = blockIdx.x; t < G1_TILES; t += gridDim.x) {
        const int bm = (t >> 2) * 128;
        for (int half = 0; half < 2; half++) {
            const int bn = (t & 3) * 256 + half * 128;
            float acc[8][8];
#pragma unroll
            for (int i = 0; i < 8; i++)
#pragma unroll
                for (int j = 0; j < 8; j++) acc[i][j] = 0.0f;

            for (int k0 = 0; k0 < D_DIM; k0 += 8) {
                __syncthreads();
                if (tid < 256) {
                    float4 a4 = *(const float4*)(x  + (size_t)(bm + lr) * D_DIM + lc + k0);
                    float4 b4 = *(const float4*)(W1 + (size_t)(bn + lr) * D_DIM + lc + k0);
                    As[(lc + 0) * 128 + lr] = a4.x; As[(lc + 1) * 128 + lr] = a4.y;
                    As[(lc + 2) * 128 + lr] = a4.z; As[(lc + 3) * 128 + lr] = a4.w;
                    Bs[(lc + 0) * 128 + lr] = b4.x; Bs[(lc + 1) * 128 + lr] = b4.y;
                    Bs[(lc + 2) * 128 + lr] = b4.z; Bs[(lc + 3) * 128 + lr] = b4.w;
                }
                __syncthreads();
                if (tid < 256) {
#pragma unroll
                    for (int kk = 0; kk < 8; kk++) {
                        float a[8], b[8];
                        *(float4*)(a)     = *(const float4*)&As[kk * 128 + ty * 8];
                        *(float4*)(a + 4) = *(const float4*)&As[kk * 128 + ty * 8 + 4];
                        *(float4*)(b)     = *(const float4*)&Bs[kk * 128 + tx * 8];
                        *(float4*)(b + 4) = *(const float4*)&Bs[kk * 128 + tx * 8 + 4];
#pragma unroll
                        for (int i = 0; i < 8; i++)
#pragma unroll
                            for (int j = 0; j < 8; j++)
                                acc[i][j] = fmaf(a[i], b[j], acc[i][j]);
                    }
                }
            }

            if (tid < 256) {
                float bias[8];
                *(float4*)(bias)     = *(const float4*)&b1[bn + tx * 8];
                *(float4*)(bias + 4) = *(const float4*)&b1[bn + tx * 8 + 4];
#pragma unroll
                for (int i = 0; i < 8; i++) {
                    const int row = bm + ty * 8 + i;
                    float o[8];
#pragma unroll
                    for (int j = 0; j < 8; j++)
                        o[j] = gelu_erf(acc[i][j] + bias[j]);
                    float* dst = Hout + (size_t)row * H_DIM + bn + tx * 8;
                    *(float4*)(dst)     = make_float4(o[0], o[1], o[2], o[3]);
                    *(float4*)(dst + 4) = make_float4(o[4], o[5], o[6], o[7]);
                }
            }
            __syncthreads();
        }
    }
#endif
}

// ============================================================================
// GEMM2: logits = (H @ W2^T + b2)/temp; top-2 softmax.  3xTF32, 4-stage pipe,
// in-register split. 288 threads. (unchanged from round 6)
// ============================================================================
#define NIT2 (H_DIM / 32)
#define STAGE2_BYTES 49152
#define OFF2_HLO 16384
#define OFF2_WHI 32768
#define OFF2_WLO 40960
#define GEMM2_SMEM (1024 + 4 * STAGE2_BYTES)

#define IDESC_G2 ((1u << 4) | (2u << 7) | (2u << 10) | ((64u / 8) << 17) | ((128u / 16) << 24))

extern "C" __global__ void __launch_bounds__(288, 1) gemm2_kernel(
    const float* __restrict__ Hin, const float* __restrict__ W2,
    const float* __restrict__ b2, const float* __restrict__ log_temp,
    float* __restrict__ out)
{
    extern __shared__ __align__(1024) char smem[];
    const int tid = threadIdx.x;
    const int bm = blockIdx.x * 128;

#if HAS_TCGEN05
    const uint32_t sbase = smem_u32(smem);

    if (tid == 0) {
#pragma unroll
        for (int s = 0; s < 4; s++) {
            mbar_init(sbase + 64 + 16 * s, 256);
            mbar_init(sbase + 64 + 16 * s + 8, 1);
        }
    }
    if (tid >= 256) tc_alloc(sbase, 64);
    __syncthreads();

    uint32_t tmem_base;
    asm volatile("ld.shared.b32 %0, [%1];" : "=r"(tmem_base) : "r"(sbase));

    if (tid < 256) {
        const int r0 = tid >> 3;
        const int c4 = tid & 7;
        uint32_t offH[4], offW[2];
#pragma unroll
        for (int j = 0; j < 4; j++)
            offH[j] = SWZ128((uint32_t)(r0 + 32 * j) * 128 + c4 * 16);
#pragma unroll
        for (int j = 0; j < 2; j++)
            offW[j] = SWZ128((uint32_t)(r0 + 32 * j) * 128 + c4 * 16);

        const float* pH = Hin + (size_t)(bm + r0) * H_DIM + c4 * 4;
        const float* pW = W2  + (size_t)r0 * H_DIM + c4 * 4;

        uint32_t pe[4] = {1, 1, 1, 1};

        for (int ii = 0; ii < NIT2 / 4; ii++) {
#pragma unroll
            for (int s = 0; s < 4; s++) {
                const int i = ii * 4 + s;
                const uint32_t mb_full  = sbase + 64 + 16 * s;
                const uint32_t mb_empty = mb_full + 8;
                mbar_wait(mb_empty, pe[s]); pe[s] ^= 1;

                const int k0 = i * 32;
                char* st = smem + 1024 + s * STAGE2_BYTES;
#pragma unroll
                for (int j = 0; j < 4; j++) {
                    float4 v = *(const float4*)(pH + (size_t)(32 * j) * H_DIM + k0);
                    float4 h, l; split4(v, h, l);
                    *(float4*)(st + offH[j])            = h;
                    *(float4*)(st + OFF2_HLO + offH[j]) = l;
                }
#pragma unroll
                for (int j = 0; j < 2; j++) {
                    float4 v = *(const float4*)(pW + (size_t)(32 * j) * H_DIM + k0);
                    float4 h, l; split4(v, h, l);
                    *(float4*)(st + OFF2_WHI + offW[j]) = h;
                    *(float4*)(st + OFF2_WLO + offW[j]) = l;
                }
                fence_proxy_async_cta();
                mbar_arrive(mb_full);
            }
        }

#pragma unroll
        for (int s = 0; s < 4; s++)
            mbar_wait(sbase + 64 + 16 * s + 8, pe[s]);
        tc_fence_after();
    } else if (tid == 256) {
        uint32_t pf[4] = {0, 0, 0, 0};
        for (int ii = 0; ii < NIT2 / 4; ii++) {
#pragma unroll
            for (int s = 0; s < 4; s++) {
                const int i = ii * 4 + s;
                const uint32_t mb_full  = sbase + 64 + 16 * s;
                const uint32_t mb_empty = mb_full + 8;
                mbar_wait(mb_full, pf[s]); pf[s] ^= 1;

                uint32_t sb = sbase + 1024 + s * STAGE2_BYTES;
                uint64_t dHh = make_desc_sw128(sb);
                uint64_t dHl = make_desc_sw128(sb + OFF2_HLO);
                uint64_t dWh = make_desc_sw128(sb + OFF2_WHI);
                uint64_t dWl = make_desc_sw128(sb + OFF2_WLO);
#pragma unroll
                for (int ks = 0; ks < 4; ks++) {
                    mma_tf32_ss(tmem_base, dHh + 2 * ks, dWh + 2 * ks, IDESC_G2,
                                (i == 0 && ks == 0) ? 0u : 1u);
                    mma_tf32_ss(tmem_base, dHh + 2 * ks, dWl + 2 * ks, IDESC_G2, 1u);
                    mma_tf32_ss(tmem_base, dHl + 2 * ks, dWh + 2 * ks, IDESC_G2, 1u);
                }
                tc_commit(mb_empty);
            }
        }
    }
    __syncthreads();

    float* Ls  = (float*)(smem + 1024);            // [128][65]
    float* p1s = (float*)(smem + 1024 + 33280);
    float* p2s = p1s + 128;
    int*   i1s = (int*)(p2s + 128);
    int*   i2s = i1s + 128;

    float t = expf(*log_temp);
    t = fminf(fmaxf(t, 1e-3f), 100.0f);
    const float it = 1.0f / t;

    if (tid < 256) {
        const int w = tid >> 5, lane = tid & 31;
        const int row = (w & 3) * 32 + lane;
        const int colbase = (w >> 2) * 32;
        uint32_t r[32];
        TC_LD_X32(r, tmem_base + colbase);
        tc_wait_ld();
#pragma unroll
        for (int c = 0; c < 32; c++)
            Ls[row * 65 + colbase + c] =
                (__uint_as_float(r[c]) + b2[colbase + c]) * it;
    }
    __syncthreads();

    if (tid < 128) {
        float m1 = -INFINITY, m2 = -INFINITY;
        int i1 = -1, i2 = -1;
#pragma unroll 8
        for (int e = 0; e < E_DIM; e++) {
            float v = Ls[tid * 65 + e];
            if (v > m1) { m2 = m1; i2 = i1; m1 = v; i1 = e; }
            else if (v > m2) { m2 = v; i2 = e; }
        }
        float ed = expf(m2 - m1);
        float s = 1.0f / (1.0f + ed);
        p1s[tid] = s;
        p2s[tid] = ed * s;
        i1s[tid] = i1;
        i2s[tid] = i2;
    }
    __syncthreads();

    if (tid < 256) {
        for (int idx = tid; idx < 128 * E_DIM; idx += 256) {
            const int r = idx >> 6;
            const int e = idx & 63;
            float v = 0.0f;
            if (e == i1s[r]) v = p1s[r];
            else if (e == i2s[r]) v = p2s[r];
            out[(size_t)(bm + r) * E_DIM + e] = v;
        }
    }

    __syncthreads();
    if (tid >= 256) tc_dealloc(tmem_base, 64);

#else  // ---------- FFMA fallback (generic pass) -----------------------------
    float* Hs  = (float*)smem;
    float* Ws  = Hs + 16 * 128;
    float* Ls  = Ws + 16 * 64;
    float* p1s = Ls + 128 * 65;
    float* p2s = p1s + 128;
    int*   i1s = (int*)(p2s + 128);
    int*   i2s = i1s + 128;

    const int tx = tid & 15;
    const int ty = tid >> 4;
    const int hr0 = tid >> 2;
    const int hc0 = (tid & 3) * 4;
    const int hr1 = (tid + 256) >> 2;
    const int wr = tid >> 2;
    const int wc = (tid & 3) * 4;

    float acc[8][4];
#pragma unroll
    for (int i = 0; i < 8; i++)
#pragma unroll
        for (int j = 0; j < 4; j++) acc[i][j] = 0.0f;

    for (int k0 = 0; k0 < H_DIM; k0 += 16) {
        __syncthreads();
        if (tid < 256) {
            float4 h0 = *(const float4*)(Hin + (size_t)(bm + hr0) * H_DIM + k0 + hc0);
            float4 h1 = *(const float4*)(Hin + (size_t)(bm + hr1) * H_DIM + k0 + hc0);
            float4 w4 = *(const float4*)(W2  + (size_t)wr * H_DIM + k0 + wc);
            Hs[(hc0 + 0) * 128 + hr0] = h0.x; Hs[(hc0 + 1) * 128 + hr0] = h0.y;
            Hs[(hc0 + 2) * 128 + hr0] = h0.z; Hs[(hc0 + 3) * 128 + hr0] = h0.w;
            Hs[(hc0 + 0) * 128 + hr1] = h1.x; Hs[(hc0 + 1) * 128 + hr1] = h1.y;
            Hs[(hc0 + 2) * 128 + hr1] = h1.z; Hs[(hc0 + 3) * 128 + hr1] = h1.w;
            Ws[(wc + 0) * 64 + wr] = w4.x; Ws[(wc + 1) * 64 + wr] = w4.y;
            Ws[(wc + 2) * 64 + wr] = w4.z; Ws[(wc + 3) * 64 + wr] = w4.w;
        }
        __syncthreads();
        if (tid < 256) {
#pragma unroll
            for (int kk = 0; kk < 16; kk++) {
                float a[8], b[4];
                *(float4*)(a)     = *(const float4*)&Hs[kk * 128 + ty * 8];
                *(float4*)(a + 4) = *(const float4*)&Hs[kk * 128 + ty * 8 + 4];
                *(float4*)(b)     = *(const float4*)&Ws[kk * 64 + tx * 4];
#pragma unroll
                for (int i = 0; i < 8; i++)
#pragma unroll
                    for (int j = 0; j < 4; j++)
                        acc[i][j] = fmaf(a[i], b[j], acc[i][j]);
            }
        }
    }

    float t = expf(*log_temp);
    t = fminf(fmaxf(t, 1e-3f), 100.0f);
    const float it = 1.0f / t;

    if (tid < 256) {
#pragma unroll
        for (int i = 0; i < 8; i++)
#pragma unroll
            for (int j = 0; j < 4; j++) {
                const int col = tx * 4 + j;
                Ls[(ty * 8 + i) * 65 + col] = (acc[i][j] + b2[col]) * it;
            }
    }
    __syncthreads();

    if (tid < 128) {
        float m1 = -INFINITY, m2 = -INFINITY;
        int i1 = -1, i2 = -1;
#pragma unroll 8
        for (int e = 0; e < E_DIM; e++) {
            float v = Ls[tid * 65 + e];
            if (v > m1) { m2 = m1; i2 = i1; m1 = v; i1 = e; }
            else if (v > m2) { m2 = v; i2 = e; }
        }
        float ed = expf(m2 - m1);
        float s = 1.0f / (1.0f + ed);
        p1s[tid] = s;
        p2s[tid] = ed * s;
        i1s[tid] = i1;
        i2s[tid] = i2;
    }
    __syncthreads();

    if (tid < 256) {
        for (int idx = tid; idx < 128 * E_DIM; idx += 256) {
            const int r = idx >> 6;
            const int e = idx & 63;
            float v = 0.0f;
            if (e == i1s[r]) v = p1s[r];
            else if (e == i2s[r]) v = p2s[r];
            out[(size_t)(bm + r) * E_DIM + e] = v;
        }
    }
#endif
}

// ---------------- launcher ---------------------------------------------------
extern "C" void kernel_launch(void* const* d_in, const int* in_sizes, int n_in,
                              void* d_out, int out_size) {
    const float* x  = (const float*)d_in[0];
    const float* W1 = (const float*)d_in[1];
    const float* b1 = (const float*)d_in[2];
    const float* W2 = (const float*)d_in[3];
    const float* b2 = (const float*)d_in[4];
    const float* lt = (const float*)d_in[5];
    float* out = (float*)d_out;

    const int M = in_sizes[0] / D_DIM;   // 65536

    float* Hbuf;
    cudaGetSymbolAddress((void**)&Hbuf, g_H);

    static int nsm = 0;
    if (!nsm) {
        cudaDeviceGetAttribute(&nsm, cudaDevAttrMultiProcessorCount, 0);
        cudaFuncSetAttribute(gemm1_kernel,
                             cudaFuncAttributeMaxDynamicSharedMemorySize, GEMM1_SMEM);
        cudaFuncSetAttribute(gemm2_kernel,
                             cudaFuncAttributeMaxDynamicSharedMemorySize, GEMM2_SMEM);
    }
    const int g1 = nsm & ~1;   // even grid for 2-CTA clusters

    gemm1_kernel<<<g1, 416, GEMM1_SMEM>>>(x, W1, b1, Hbuf);

    dim3 grid2(M / 128);
    gemm2_kernel<<<grid2, 288, GEMM2_SMEM>>>(Hbuf, W2, b2, lt, out);
}

// round 10
// speedup vs baseline: 1.0362x; 1.0362x over previous
#include <cuda_runtime.h>
#include <math.h>
#include <stdint.h>

#define D_DIM 1024
#define H_DIM 1024
#define E_DIM 64
#define M_TOTAL 65536
#define G1_TILES ((M_TOTAL / 128) * (H_DIM / 256))     // 2048 (fallback)
#define PAIR_TILES ((M_TOTAL / 256) * (H_DIM / 256))   // 1024 (cg2)

#if defined(__CUDA_ARCH__) && (__CUDA_ARCH__ >= 1000) && \
    (defined(__CUDA_ARCH_FEAT_SM103_ALL) || defined(__CUDA_ARCH_FEAT_SM100_ALL) || \
     defined(__CUDA_ARCH_SPECIFIC__) || defined(__CUDA_ARCH_FAMILY_SPECIFIC__))
#define HAS_TCGEN05 1
#else
#define HAS_TCGEN05 0
#endif

__device__ float g_H[(size_t)M_TOTAL * H_DIM];   // 256 MB hidden activations

// ---------------- PTX helpers ------------------------------------------------
__device__ __forceinline__ uint32_t smem_u32(const void* p) {
    uint32_t a;
    asm("{ .reg .u64 t; cvta.to.shared.u64 t, %1; cvt.u32.u64 %0, t; }"
        : "=r"(a) : "l"(p));
    return a;
}
__device__ __forceinline__ uint32_t cluster_rank() {
    uint32_t r;
    asm("mov.u32 %0, %%cluster_ctarank;" : "=r"(r));
    return r;
}

#define SWZ128(o) ((o) ^ (((o) >> 3) & 0x70))

__device__ __forceinline__ void mbar_init(uint32_t mbar, uint32_t cnt) {
    asm volatile("mbarrier.init.shared.b64 [%0], %1;" :: "r"(mbar), "r"(cnt) : "memory");
}
__device__ __forceinline__ void mbar_wait(uint32_t mbar, uint32_t parity) {
    asm volatile(
        "{\n\t"
        ".reg .pred P;\n\t"
        "WL%=:\n\t"
        "mbarrier.try_wait.parity.shared::cta.b64 P, [%0], %1, 0x989680;\n\t"
        "@P bra WD%=;\n\t"
        "bra WL%=;\n\t"
        "WD%=:\n\t"
        "}"
        :: "r"(mbar), "r"(parity) : "memory");
}
__device__ __forceinline__ void mbar_arrive(uint32_t mbar) {
    asm volatile("mbarrier.arrive.shared.b64 _, [%0];" :: "r"(mbar) : "memory");
}
// Arrive on the leader (rank 0) CTA's mbarrier at the same smem offset.
__device__ __forceinline__ void mbar_arrive_leader(uint32_t local_mbar) {
    asm volatile(
        "{\n\t"
        ".reg .b32 ra;\n\t"
        "mapa.shared::cluster.u32 ra, %0, 0;\n\t"
        "mbarrier.arrive.shared::cluster.b64 _, [ra];\n\t"
        "}"
        :: "r"(local_mbar) : "memory");
}
__device__ __forceinline__ void fence_proxy_async_gen() {
    asm volatile("fence.proxy.async;" ::: "memory");
}
__device__ __forceinline__ void fence_proxy_async_cta() {
    asm volatile("fence.proxy.async.shared::cta;" ::: "memory");
}
__device__ __forceinline__ void cluster_sync() {
    asm volatile("barrier.cluster.arrive.aligned;" ::: "memory");
    asm volatile("barrier.cluster.wait.aligned;" ::: "memory");
}

__device__ __forceinline__ float tf32_rnd(float a) {
    uint32_t r;
    asm("cvt.rna.tf32.f32 %0, %1;" : "=r"(r) : "f"(a));
    return __uint_as_float(r);
}
__device__ __forceinline__ void split4(float4 v, float4& h, float4& l) {
    h.x = tf32_rnd(v.x); l.x = tf32_rnd(v.x - h.x);
    h.y = tf32_rnd(v.y); l.y = tf32_rnd(v.y - h.y);
    h.z = tf32_rnd(v.z); l.z = tf32_rnd(v.z - h.z);
    h.w = tf32_rnd(v.w); l.w = tf32_rnd(v.w - h.w);
}

#if HAS_TCGEN05
__device__ __forceinline__ uint64_t make_desc_sw128(uint32_t addr) {
    const uint64_t base = (2ull << 61) | (1ull << 46) | (64ull << 32) | (1ull << 16);
    return base | ((uint64_t)(addr >> 4) & 0x3FFF);
}
__device__ __forceinline__ void mma_tf32_ss(uint32_t d_tmem, uint64_t a_desc,
                                            uint64_t b_desc, uint32_t idesc,
                                            uint32_t enable_d) {
    asm volatile(
        "{\n\t"
        ".reg .pred p;\n\t"
        "setp.ne.u32 p, %5, 0;\n\t"
        "tcgen05.mma.cta_group::1.kind::tf32 [%0], %1, %2, %3, {%4, %4, %4, %4}, p;\n\t"
        "}"
        :: "r"(d_tmem), "l"(a_desc), "l"(b_desc), "r"(idesc), "r"(0u), "r"(enable_d)
        : "memory");
}
__device__ __forceinline__ void mma_tf32_ss_cg2(uint32_t d_tmem, uint64_t a_desc,
                                                uint64_t b_desc, uint32_t idesc,
                                                uint32_t enable_d) {
    asm volatile(
        "{\n\t"
        ".reg .pred p;\n\t"
        "setp.ne.u32 p, %5, 0;\n\t"
        "tcgen05.mma.cta_group::2.kind::tf32 [%0], %1, %2, %3, "
        "{%4, %4, %4, %4, %4, %4, %4, %4}, p;\n\t"
        "}"
        :: "r"(d_tmem), "l"(a_desc), "l"(b_desc), "r"(idesc), "r"(0u), "r"(enable_d)
        : "memory");
}
__device__ __forceinline__ void tc_commit(uint32_t mbar) {
    asm volatile(
        "tcgen05.commit.cta_group::1.mbarrier::arrive::one.shared::cluster.b64 [%0];"
        :: "r"(mbar) : "memory");
}
__device__ __forceinline__ void tc_commit_mc_cg2(uint32_t mbar, uint16_t mask) {
    asm volatile(
        "tcgen05.commit.cta_group::2.mbarrier::arrive::one.shared::cluster.multicast::cluster.b64 [%0], %1;"
        :: "r"(mbar), "h"(mask) : "memory");
}
__device__ __forceinline__ void tc_alloc(uint32_t slot, uint32_t ncols) {
    asm volatile("tcgen05.alloc.cta_group::1.sync.aligned.shared::cta.b32 [%0], %1;"
                 :: "r"(slot), "r"(ncols) : "memory");
}
__device__ __forceinline__ void tc_alloc_cg2(uint32_t slot, uint32_t ncols) {
    asm volatile("tcgen05.alloc.cta_group::2.sync.aligned.shared::cta.b32 [%0], %1;"
                 :: "r"(slot), "r"(ncols) : "memory");
}
__device__ __forceinline__ void tc_dealloc(uint32_t tmem, uint32_t ncols) {
    asm volatile("tcgen05.relinquish_alloc_permit.cta_group::1.sync.aligned;");
    asm volatile("tcgen05.dealloc.cta_group::1.sync.aligned.b32 %0, %1;" :: "r"(tmem), "r"(ncols));
}
__device__ __forceinline__ void tc_dealloc_cg2(uint32_t tmem, uint32_t ncols) {
    asm volatile("tcgen05.relinquish_alloc_permit.cta_group::2.sync.aligned;");
    asm volatile("tcgen05.dealloc.cta_group::2.sync.aligned.b32 %0, %1;" :: "r"(tmem), "r"(ncols));
}
__device__ __forceinline__ void tc_fence_after() {
    asm volatile("tcgen05.fence::after_thread_sync;" ::: "memory");
}
__device__ __forceinline__ void tc_fence_before() {
    asm volatile("tcgen05.fence::before_thread_sync;" ::: "memory");
}
__device__ __forceinline__ void tc_wait_ld() {
    asm volatile("tcgen05.wait::ld.sync.aligned;" ::: "memory");
}

#define TC_LD_X32(r, a)                                                       \
    asm volatile(                                                             \
        "tcgen05.ld.sync.aligned.32x32b.x32.b32 "                             \
        "{%0, %1, %2, %3, %4, %5, %6, %7, "                                   \
        " %8, %9, %10, %11, %12, %13, %14, %15, "                             \
        " %16, %17, %18, %19, %20, %21, %22, %23, "                           \
        " %24, %25, %26, %27, %28, %29, %30, %31}, [%32];"                    \
        : "=r"((r)[0]),  "=r"((r)[1]),  "=r"((r)[2]),  "=r"((r)[3]),          \
          "=r"((r)[4]),  "=r"((r)[5]),  "=r"((r)[6]),  "=r"((r)[7]),          \
          "=r"((r)[8]),  "=r"((r)[9]),  "=r"((r)[10]), "=r"((r)[11]),         \
          "=r"((r)[12]), "=r"((r)[13]), "=r"((r)[14]), "=r"((r)[15]),         \
          "=r"((r)[16]), "=r"((r)[17]), "=r"((r)[18]), "=r"((r)[19]),         \
          "=r"((r)[20]), "=r"((r)[21]), "=r"((r)[22]), "=r"((r)[23]),         \
          "=r"((r)[24]), "=r"((r)[25]), "=r"((r)[26]), "=r"((r)[27]),         \
          "=r"((r)[28]), "=r"((r)[29]), "=r"((r)[30]), "=r"((r)[31])          \
        : "r"(a))
#endif  // HAS_TCGEN05

__device__ __forceinline__ float gelu_erf(float v) {
    return 0.5f * v * (1.0f + erff(v * 0.7071067811865476f));
}

// ============================================================================
// GEMM1 (persistent, cta_group::2, hierarchical signaling):
// H = gelu(x @ W1^T + b1). 3xTF32. Pair-tile M=256 x N=256, BK=32, 3-stage.
// 448 thr/CTA: warps 0-7 producers | warp 8 MMA (leader) | 9-12 epilogue |
// warp 13 forwarder (lane0: full, lane1: dfree).
// ============================================================================
#define BK 32
#define NIT (D_DIM / BK)
#define NSTG 3
#define STG1_BYTES 65536
#define OFF_ALO 16384
#define OFF_BHI 32768
#define OFF_BLO 49152
#define GEMM1_SMEM (1024 + NSTG * STG1_BYTES)

// mbar smem offsets
#define MB_FULL(s)   (64 + 16 * (s))         // leader, cnt 2
#define MB_EMPTY(s)  (64 + 16 * (s) + 8)     // per-CTA, cnt 1 (mc commit)
#define MB_LF(s)     (112 + 16 * (s))        // per-CTA local full, cnt 8
#define MB_TDONE(b)  (160 + 16 * (b))        // per-CTA, cnt 1 (mc commit)
#define MB_DFREE(b)  (160 + 16 * (b) + 8)    // leader, cnt 2
#define MB_LDF(b)    (192 + 16 * (b))        // per-CTA local dfree, cnt 4

// cg2 idesc: dtype f32, a/b tf32, N=256, M=256
#define IDESC_CG2 ((1u << 4) | (2u << 7) | (2u << 10) | ((256u / 8) << 17) | ((256u / 16) << 24))

extern "C" __global__ void __launch_bounds__(448, 1) __cluster_dims__(2, 1, 1)
gemm1_kernel(
    const float* __restrict__ x, const float* __restrict__ W1,
    const float* __restrict__ b1, float* __restrict__ Hout)
{
    extern __shared__ __align__(1024) char smem[];
    const int tid = threadIdx.x;

#if HAS_TCGEN05
    const uint32_t sbase = smem_u32(smem);
    const uint32_t rank = cluster_rank();
    const int pair = blockIdx.x >> 1;
    const int npairs = gridDim.x >> 1;
    const int lane = tid & 31;

    if (tid == 0) {
#pragma unroll
        for (int s = 0; s < NSTG; s++) {
            mbar_init(sbase + MB_FULL(s), 2);
            mbar_init(sbase + MB_EMPTY(s), 1);
            mbar_init(sbase + MB_LF(s), 8);
        }
#pragma unroll
        for (int b = 0; b < 2; b++) {
            mbar_init(sbase + MB_TDONE(b), 1);
            mbar_init(sbase + MB_DFREE(b), 2);
            mbar_init(sbase + MB_LDF(b), 4);
        }
    }
    if (tid >= 256 && tid < 288) tc_alloc_cg2(sbase, 512);
    __syncthreads();
    cluster_sync();   // barriers + TMEM visible before cross-CTA traffic

    uint32_t tmem_base;
    asm volatile("ld.shared.b32 %0, [%1];" : "=r"(tmem_base) : "r"(sbase));

    if (tid < 256) {
        // ---------------- producers: fill local A-half / B-half --------------
        const int r0 = tid >> 3;        // 0..31
        const int c4 = tid & 7;
        uint32_t off[4];
#pragma unroll
        for (int j = 0; j < 4; j++)
            off[j] = SWZ128((uint32_t)(r0 + 32 * j) * 128 + c4 * 16);

        uint32_t pe[NSTG] = {1, 1, 1};
        int s = 0;

        for (int t = pair; t < PAIR_TILES; t += npairs) {
            const int bm = (t >> 2) * 256 + rank * 128;
            const int bn = (t & 3) * 256 + rank * 128;
            const float* pA = x  + (size_t)(bm + r0) * D_DIM + c4 * 4;
            const float* pB = W1 + (size_t)(bn + r0) * D_DIM + c4 * 4;

            for (int i = 0; i < NIT; i++) {
                mbar_wait(sbase + MB_EMPTY(s), pe[s]); pe[s] ^= 1;

                const int k0 = i * BK;
                char* st = smem + 1024 + s * STG1_BYTES;
#pragma unroll
                for (int j = 0; j < 4; j++) {
                    float4 v = *(const float4*)(pA + (size_t)(32 * j) * D_DIM + k0);
                    float4 h, l; split4(v, h, l);
                    *(float4*)(st + off[j])           = h;
                    *(float4*)(st + OFF_ALO + off[j]) = l;
                }
#pragma unroll
                for (int j = 0; j < 4; j++) {
                    float4 v = *(const float4*)(pB + (size_t)(32 * j) * D_DIM + k0);
                    float4 h, l; split4(v, h, l);
                    *(float4*)(st + OFF_BHI + off[j]) = h;
                    *(float4*)(st + OFF_BLO + off[j]) = l;
                }
                fence_proxy_async_gen();
                __syncwarp();
                if (lane == 0) mbar_arrive(sbase + MB_LF(s));   // local, cnt 8
                s = (s == NSTG - 1) ? 0 : s + 1;
            }
        }
    } else if (tid == 256 && rank == 0) {
        // ---------------- MMA issuer (leader only) ---------------------------
        uint32_t pf[NSTG] = {0, 0, 0}, pd[2] = {0, 0};
        int s = 0, lt = 0;
        for (int t = pair; t < PAIR_TILES; t += npairs) {
            const int b = lt & 1;
            if (lt >= 2) { mbar_wait(sbase + MB_DFREE(b), pd[b]); pd[b] ^= 1; }
            const uint32_t dD = tmem_base + b * 256;

            for (int i = 0; i < NIT; i++) {
                mbar_wait(sbase + MB_FULL(s), pf[s]); pf[s] ^= 1;

                uint32_t sb = sbase + 1024 + s * STG1_BYTES;
                uint64_t dAh = make_desc_sw128(sb);
                uint64_t dAl = make_desc_sw128(sb + OFF_ALO);
                uint64_t dBh = make_desc_sw128(sb + OFF_BHI);
                uint64_t dBl = make_desc_sw128(sb + OFF_BLO);
#pragma unroll
                for (int ks = 0; ks < 4; ks++) {
                    mma_tf32_ss_cg2(dD, dAh + 2 * ks, dBh + 2 * ks, IDESC_CG2,
                                    (i == 0 && ks == 0) ? 0u : 1u);
                    mma_tf32_ss_cg2(dD, dAh + 2 * ks, dBl + 2 * ks, IDESC_CG2, 1u);
                    mma_tf32_ss_cg2(dD, dAl + 2 * ks, dBh + 2 * ks, IDESC_CG2, 1u);
                }
                tc_commit_mc_cg2(sbase + MB_EMPTY(s), 0x3);   // both CTAs
                s = (s == NSTG - 1) ? 0 : s + 1;
            }
            tc_commit_mc_cg2(sbase + MB_TDONE(b), 0x3);
            lt++;
        }
    } else if (tid >= 288 && tid < 416) {
        // ---------------- epilogue: 4 warps, local 128 rows x 256 cols -------
        const int sub = (tid >> 5) & 3;
        uint32_t pt[2] = {0, 0};
        int lt = 0;
        for (int t = pair; t < PAIR_TILES; t += npairs) {
            const int b = lt & 1;
            mbar_wait(sbase + MB_TDONE(b), pt[b]); pt[b] ^= 1;
            tc_fence_after();

            const int bm = (t >> 2) * 256 + rank * 128;
            const int bn = (t & 3) * 256;
            const int row = bm + sub * 32 + lane;
            float* hrow = Hout + (size_t)row * H_DIM + bn;
            const float* brow = b1 + bn;
            const uint32_t dD = tmem_base + b * 256;
#pragma unroll
            for (int ch = 0; ch < 8; ch++) {
                uint32_t r[32];
                TC_LD_X32(r, dD + ch * 32);
                tc_wait_ld();
#pragma unroll
                for (int q = 0; q < 8; q++) {
                    float4 bias = *(const float4*)(brow + ch * 32 + q * 4);
                    float4 o;
                    o.x = gelu_erf(__uint_as_float(r[q * 4 + 0]) + bias.x);
                    o.y = gelu_erf(__uint_as_float(r[q * 4 + 1]) + bias.y);
                    o.z = gelu_erf(__uint_as_float(r[q * 4 + 2]) + bias.z);
                    o.w = gelu_erf(__uint_as_float(r[q * 4 + 3]) + bias.w);
                    *(float4*)(hrow + ch * 32 + q * 4) = o;
                }
            }
            tc_fence_before();
            __syncwarp();
            if (lane == 0) mbar_arrive(sbase + MB_LDF(b));   // local, cnt 4
            lt++;
        }
    } else if (tid >= 416) {
        // ---------------- forwarder warp (both ranks) -------------------------
        if (lane == 0) {
            // full path: mirror each local-full to leader's full[s]
            uint32_t plf[NSTG] = {0, 0, 0};
            int s = 0;
            for (int t = pair; t < PAIR_TILES; t += npairs) {
                for (int i = 0; i < NIT; i++) {
                    mbar_wait(sbase + MB_LF(s), plf[s]); plf[s] ^= 1;
                    mbar_arrive_leader(sbase + MB_FULL(s));
                    s = (s == NSTG - 1) ? 0 : s + 1;
                }
            }
        } else if (lane == 1) {
            // dfree path: one forward per tile
            uint32_t pld[2] = {0, 0};
            int lt = 0;
            for (int t = pair; t < PAIR_TILES; t += npairs) {
                const int b = lt & 1;
                mbar_wait(sbase + MB_LDF(b), pld[b]); pld[b] ^= 1;
                mbar_arrive_leader(sbase + MB_DFREE(b));
                lt++;
            }
        }
    }

    __syncthreads();
    cluster_sync();   // all peer-smem reads done before dealloc
    if (tid >= 256 && tid < 288) tc_dealloc_cg2(tmem_base, 512);
    cluster_sync();

#else  // ---------- FFMA fallback (generic pass; persistent) -----------------
    float* As = (float*)smem;
    float* Bs = As + 8 * 128;

    const int tx = tid & 15;
    const int ty = tid >> 4;
    const int lr = tid >> 1;
    const int lc = (tid & 1) * 4;

    for (int t = blockIdx.x; t < G1_TILES; t += gridDim.x) {
        const int bm = (t >> 2) * 128;
        for (int half = 0; half < 2; half++) {
            const int bn = (t & 3) * 256 + half * 128;
            float acc[8][8];
#pragma unroll
            for (int i = 0; i < 8; i++)
#pragma unroll
                for (int j = 0; j < 8; j++) acc[i][j] = 0.0f;

            for (int k0 = 0; k0 < D_DIM; k0 += 8) {
                __syncthreads();
                if (tid < 256) {
                    float4 a4 = *(const float4*)(x  + (size_t)(bm + lr) * D_DIM + lc + k0);
                    float4 b4 = *(const float4*)(W1 + (size_t)(bn + lr) * D_DIM + lc + k0);
                    As[(lc + 0) * 128 + lr] = a4.x; As[(lc + 1) * 128 + lr] = a4.y;
                    As[(lc + 2) * 128 + lr] = a4.z; As[(lc + 3) * 128 + lr] = a4.w;
                    Bs[(lc + 0) * 128 + lr] = b4.x; Bs[(lc + 1) * 128 + lr] = b4.y;
                    Bs[(lc + 2) * 128 + lr] = b4.z; Bs[(lc + 3) * 128 + lr] = b4.w;
                }
                __syncthreads();
                if (tid < 256) {
#pragma unroll
                    for (int kk = 0; kk < 8; kk++) {
                        float a[8], b[8];
                        *(float4*)(a)     = *(const float4*)&As[kk * 128 + ty * 8];
                        *(float4*)(a + 4) = *(const float4*)&As[kk * 128 + ty * 8 + 4];
                        *(float4*)(b)     = *(const float4*)&Bs[kk * 128 + tx * 8];
                        *(float4*)(b + 4) = *(const float4*)&Bs[kk * 128 + tx * 8 + 4];
#pragma unroll
                        for (int i = 0; i < 8; i++)
#pragma unroll
                            for (int j = 0; j < 8; j++)
                                acc[i][j] = fmaf(a[i], b[j], acc[i][j]);
                    }
                }
            }

            if (tid < 256) {
                float bias[8];
                *(float4*)(bias)     = *(const float4*)&b1[bn + tx * 8];
                *(float4*)(bias + 4) = *(const float4*)&b1[bn + tx * 8 + 4];
#pragma unroll
                for (int i = 0; i < 8; i++) {
                    const int row = bm + ty * 8 + i;
                    float o[8];
#pragma unroll
                    for (int j = 0; j < 8; j++)
                        o[j] = gelu_erf(acc[i][j] + bias[j]);
                    float* dst = Hout + (size_t)row * H_DIM + bn + tx * 8;
                    *(float4*)(dst)     = make_float4(o[0], o[1], o[2], o[3]);
                    *(float4*)(dst + 4) = make_float4(o[4], o[5], o[6], o[7]);
                }
            }
            __syncthreads();
        }
    }
#endif
}

// ============================================================================
// GEMM2: logits = (H @ W2^T + b2)/temp; top-2 softmax.  3xTF32, 4-stage pipe,
// in-register split. 288 threads. (unchanged, proven 123 us)
// ============================================================================
#define NIT2 (H_DIM / 32)
#define STAGE2_BYTES 49152
#define OFF2_HLO 16384
#define OFF2_WHI 32768
#define OFF2_WLO 40960
#define GEMM2_SMEM (1024 + 4 * STAGE2_BYTES)

#define IDESC_G2 ((1u << 4) | (2u << 7) | (2u << 10) | ((64u / 8) << 17) | ((128u / 16) << 24))

extern "C" __global__ void __launch_bounds__(288, 1) gemm2_kernel(
    const float* __restrict__ Hin, const float* __restrict__ W2,
    const float* __restrict__ b2, const float* __restrict__ log_temp,
    float* __restrict__ out)
{
    extern __shared__ __align__(1024) char smem[];
    const int tid = threadIdx.x;
    const int bm = blockIdx.x * 128;

#if HAS_TCGEN05
    const uint32_t sbase = smem_u32(smem);

    if (tid == 0) {
#pragma unroll
        for (int s = 0; s < 4; s++) {
            mbar_init(sbase + 64 + 16 * s, 256);
            mbar_init(sbase + 64 + 16 * s + 8, 1);
        }
    }
    if (tid >= 256) tc_alloc(sbase, 64);
    __syncthreads();

    uint32_t tmem_base;
    asm volatile("ld.shared.b32 %0, [%1];" : "=r"(tmem_base) : "r"(sbase));

    if (tid < 256) {
        const int r0 = tid >> 3;
        const int c4 = tid & 7;
        uint32_t offH[4], offW[2];
#pragma unroll
        for (int j = 0; j < 4; j++)
            offH[j] = SWZ128((uint32_t)(r0 + 32 * j) * 128 + c4 * 16);
#pragma unroll
        for (int j = 0; j < 2; j++)
            offW[j] = SWZ128((uint32_t)(r0 + 32 * j) * 128 + c4 * 16);

        const float* pH = Hin + (size_t)(bm + r0) * H_DIM + c4 * 4;
        const float* pW = W2  + (size_t)r0 * H_DIM + c4 * 4;

        uint32_t pe[4] = {1, 1, 1, 1};

        for (int ii = 0; ii < NIT2 / 4; ii++) {
#pragma unroll
            for (int s = 0; s < 4; s++) {
                const int i = ii * 4 + s;
                const uint32_t mb_full  = sbase + 64 + 16 * s;
                const uint32_t mb_empty = mb_full + 8;
                mbar_wait(mb_empty, pe[s]); pe[s] ^= 1;

                const int k0 = i * 32;
                char* st = smem + 1024 + s * STAGE2_BYTES;
#pragma unroll
                for (int j = 0; j < 4; j++) {
                    float4 v = *(const float4*)(pH + (size_t)(32 * j) * H_DIM + k0);
                    float4 h, l; split4(v, h, l);
                    *(float4*)(st + offH[j])            = h;
                    *(float4*)(st + OFF2_HLO + offH[j]) = l;
                }
#pragma unroll
                for (int j = 0; j < 2; j++) {
                    float4 v = *(const float4*)(pW + (size_t)(32 * j) * H_DIM + k0);
                    float4 h, l; split4(v, h, l);
                    *(float4*)(st + OFF2_WHI + offW[j]) = h;
                    *(float4*)(st + OFF2_WLO + offW[j]) = l;
                }
                fence_proxy_async_cta();
                mbar_arrive(mb_full);
            }
        }

#pragma unroll
        for (int s = 0; s < 4; s++)
            mbar_wait(sbase + 64 + 16 * s + 8, pe[s]);
        tc_fence_after();
    } else if (tid == 256) {
        uint32_t pf[4] = {0, 0, 0, 0};
        for (int ii = 0; ii < NIT2 / 4; ii++) {
#pragma unroll
            for (int s = 0; s < 4; s++) {
                const int i = ii * 4 + s;
                const uint32_t mb_full  = sbase + 64 + 16 * s;
                const uint32_t mb_empty = mb_full + 8;
                mbar_wait(mb_full, pf[s]); pf[s] ^= 1;

                uint32_t sb = sbase + 1024 + s * STAGE2_BYTES;
                uint64_t dHh = make_desc_sw128(sb);
                uint64_t dHl = make_desc_sw128(sb + OFF2_HLO);
                uint64_t dWh = make_desc_sw128(sb + OFF2_WHI);
                uint64_t dWl = make_desc_sw128(sb + OFF2_WLO);
#pragma unroll
                for (int ks = 0; ks < 4; ks++) {
                    mma_tf32_ss(tmem_base, dHh + 2 * ks, dWh + 2 * ks, IDESC_G2,
                                (i == 0 && ks == 0) ? 0u : 1u);
                    mma_tf32_ss(tmem_base, dHh + 2 * ks, dWl + 2 * ks, IDESC_G2, 1u);
                    mma_tf32_ss(tmem_base, dHl + 2 * ks, dWh + 2 * ks, IDESC_G2, 1u);
                }
                tc_commit(mb_empty);
            }
        }
    }
    __syncthreads();

    float* Ls  = (float*)(smem + 1024);            // [128][65]
    float* p1s = (float*)(smem + 1024 + 33280);
    float* p2s = p1s + 128;
    int*   i1s = (int*)(p2s + 128);
    int*   i2s = i1s + 128;

    float t = expf(*log_temp);
    t = fminf(fmaxf(t, 1e-3f), 100.0f);
    const float it = 1.0f / t;

    if (tid < 256) {
        const int w = tid >> 5, lane = tid & 31;
        const int row = (w & 3) * 32 + lane;
        const int colbase = (w >> 2) * 32;
        uint32_t r[32];
        TC_LD_X32(r, tmem_base + colbase);
        tc_wait_ld();
#pragma unroll
        for (int c = 0; c < 32; c++)
            Ls[row * 65 + colbase + c] =
                (__uint_as_float(r[c]) + b2[colbase + c]) * it;
    }
    __syncthreads();

    if (tid < 128) {
        float m1 = -INFINITY, m2 = -INFINITY;
        int i1 = -1, i2 = -1;
#pragma unroll 8
        for (int e = 0; e < E_DIM; e++) {
            float v = Ls[tid * 65 + e];
            if (v > m1) { m2 = m1; i2 = i1; m1 = v; i1 = e; }
            else if (v > m2) { m2 = v; i2 = e; }
        }
        float ed = expf(m2 - m1);
        float s = 1.0f / (1.0f + ed);
        p1s[tid] = s;
        p2s[tid] = ed * s;
        i1s[tid] = i1;
        i2s[tid] = i2;
    }
    __syncthreads();

    if (tid < 256) {
        for (int idx = tid; idx < 128 * E_DIM; idx += 256) {
            const int r = idx >> 6;
            const int e = idx & 63;
            float v = 0.0f;
            if (e == i1s[r]) v = p1s[r];
            else if (e == i2s[r]) v = p2s[r];
            out[(size_t)(bm + r) * E_DIM + e] = v;
        }
    }

    __syncthreads();
    if (tid >= 256) tc_dealloc(tmem_base, 64);

#else  // ---------- FFMA fallback (generic pass) -----------------------------
    float* Hs  = (float*)smem;
    float* Ws  = Hs + 16 * 128;
    float* Ls  = Ws + 16 * 64;
    float* p1s = Ls + 128 * 65;
    float* p2s = p1s + 128;
    int*   i1s = (int*)(p2s + 128);
    int*   i2s = i1s + 128;

    const int tx = tid & 15;
    const int ty = tid >> 4;
    const int hr0 = tid >> 2;
    const int hc0 = (tid & 3) * 4;
    const int hr1 = (tid + 256) >> 2;
    const int wr = tid >> 2;
    const int wc = (tid & 3) * 4;

    float acc[8][4];
#pragma unroll
    for (int i = 0; i < 8; i++)
#pragma unroll
        for (int j = 0; j < 4; j++) acc[i][j] = 0.0f;

    for (int k0 = 0; k0 < H_DIM; k0 += 16) {
        __syncthreads();
        if (tid < 256) {
            float4 h0 = *(const float4*)(Hin + (size_t)(bm + hr0) * H_DIM + k0 + hc0);
            float4 h1 = *(const float4*)(Hin + (size_t)(bm + hr1) * H_DIM + k0 + hc0);
            float4 w4 = *(const float4*)(W2  + (size_t)wr * H_DIM + k0 + wc);
            Hs[(hc0 + 0) * 128 + hr0] = h0.x; Hs[(hc0 + 1) * 128 + hr0] = h0.y;
            Hs[(hc0 + 2) * 128 + hr0] = h0.z; Hs[(hc0 + 3) * 128 + hr0] = h0.w;
            Hs[(hc0 + 0) * 128 + hr1] = h1.x; Hs[(hc0 + 1) * 128 + hr1] = h1.y;
            Hs[(hc0 + 2) * 128 + hr1] = h1.z; Hs[(hc0 + 3) * 128 + hr1] = h1.w;
            Ws[(wc + 0) * 64 + wr] = w4.x; Ws[(wc + 1) * 64 + wr] = w4.y;
            Ws[(wc + 2) * 64 + wr] = w4.z; Ws[(wc + 3) * 64 + wr] = w4.w;
        }
        __syncthreads();
        if (tid < 256) {
#pragma unroll
            for (int kk = 0; kk < 16; kk++) {
                float a[8], b[4];
                *(float4*)(a)     = *(const float4*)&Hs[kk * 128 + ty * 8];
                *(float4*)(a + 4) = *(const float4*)&Hs[kk * 128 + ty * 8 + 4];
                *(float4*)(b)     = *(const float4*)&Ws[kk * 64 + tx * 4];
#pragma unroll
                for (int i = 0; i < 8; i++)
#pragma unroll
                    for (int j = 0; j < 4; j++)
                        acc[i][j] = fmaf(a[i], b[j], acc[i][j]);
            }
        }
    }

    float t = expf(*log_temp);
    t = fminf(fmaxf(t, 1e-3f), 100.0f);
    const float it = 1.0f / t;

    if (tid < 256) {
#pragma unroll
        for (int i = 0; i < 8; i++)
#pragma unroll
            for (int j = 0; j < 4; j++) {
                const int col = tx * 4 + j;
                Ls[(ty * 8 + i) * 65 + col] = (acc[i][j] + b2[col]) * it;
            }
    }
    __syncthreads();

    if (tid < 128) {
        float m1 = -INFINITY, m2 = -INFINITY;
        int i1 = -1, i2 = -1;
#pragma unroll 8
        for (int e = 0; e < E_DIM; e++) {
            float v = Ls[tid * 65 + e];
            if (v > m1) { m2 = m1; i2 = i1; m1 = v; i1 = e; }
            else if (v > m2) { m2 = v; i2 = e; }
        }
        float ed = expf(m2 - m1);
        float s = 1.0f / (1.0f + ed);
        p1s[tid] = s;
        p2s[tid] = ed * s;
        i1s[tid] = i1;
        i2s[tid] = i2;
    }
    __syncthreads();

    if (tid < 256) {
        for (int idx = tid; idx < 128 * E_DIM; idx += 256) {
            const int r = idx >> 6;
            const int e = idx & 63;
            float v = 0.0f;
            if (e == i1s[r]) v = p1s[r];
            else if (e == i2s[r]) v = p2s[r];
            out[(size_t)(bm + r) * E_DIM + e] = v;
        }
    }
#endif
}

// ---------------- launcher ---------------------------------------------------
extern "C" void kernel_launch(void* const* d_in, const int* in_sizes, int n_in,
                              void* d_out, int out_size) {
    const float* x  = (const float*)d_in[0];
    const float* W1 = (const float*)d_in[1];
    const float* b1 = (const float*)d_in[2];
    const float* W2 = (const float*)d_in[3];
    const float* b2 = (const float*)d_in[4];
    const float* lt = (const float*)d_in[5];
    float* out = (float*)d_out;

    const int M = in_sizes[0] / D_DIM;   // 65536

    float* Hbuf;
    cudaGetSymbolAddress((void**)&Hbuf, g_H);

    static int nsm = 0;
    if (!nsm) {
        cudaDeviceGetAttribute(&nsm, cudaDevAttrMultiProcessorCount, 0);
        cudaFuncSetAttribute(gemm1_kernel,
                             cudaFuncAttributeMaxDynamicSharedMemorySize, GEMM1_SMEM);
        cudaFuncSetAttribute(gemm2_kernel,
                             cudaFuncAttributeMaxDynamicSharedMemorySize, GEMM2_SMEM);
    }
    const int g1 = nsm & ~1;   // even grid for 2-CTA clusters

    gemm1_kernel<<<g1, 448, GEMM1_SMEM>>>(x, W1, b1, Hbuf);

    dim3 grid2(M / 128);
    gemm2_kernel<<<grid2, 288, GEMM2_SMEM>>>(Hbuf, W2, b2, lt, out);
}